// round 8
// baseline (speedup 1.0000x reference)
#include <cuda_runtime.h>
#include <cuda_fp16.h>
#include <math.h>
#include <stdint.h>

// Problem constants
#define BB    2
#define NN    8192
#define DD    256
#define HH    8
#define DHD   64
#define KNB   8
#define INNER 512
#define MTOT  (BB*NN)        // 16384
#define NQKV  (3*INNER)      // 1536 = Q | K | V

// 2-term fp16 split as extended-K plain GEMM:
//   A2 = [Ah | Al], B2 = [Bh | Bh]  ->  C = A*Bh (only fp16 rounding of B)
#define K2_QKV (2*DD)        // 512
#define K2_OUT (2*INNER)     // 1024

// ---------------- static device scratch ----------------
__device__ __half g_X2 [(size_t)MTOT * K2_QKV];     // 16.8 MB
__device__ __half g_WT [(size_t)NQKV * K2_QKV];     // 1.5 MB (N-major)
__device__ __half g_WTO[(size_t)DD * K2_OUT];       // 0.5 MB (N-major)
__device__ float  g_QKV[(size_t)MTOT * NQKV];       // 100 MB
__device__ __half g_AT2[(size_t)MTOT * K2_OUT];     // 33.6 MB
__device__ int    g_IDX[(size_t)MTOT * KNB];

__device__ __forceinline__ uint32_t smem_u32(const void* p) {
    uint32_t a;
    asm("{ .reg .u64 t; cvta.to.shared.u64 t, %1; cvt.u32.u64 %0, t; }" : "=r"(a) : "l"(p));
    return a;
}
__device__ __forceinline__ void cp_async16(uint32_t s, const void* g) {
    asm volatile("cp.async.cg.shared.global [%0], [%1], 16;" :: "r"(s), "l"(g));
}
#define CP_COMMIT()  asm volatile("cp.async.commit_group;" ::: "memory")
#define CP_WAIT2()   asm volatile("cp.async.wait_group 2;" ::: "memory")

__device__ __forceinline__ void split_f16(float v, __half& h, __half& l) {
    h = __float2half(v);
    l = __float2half(v - __half2float(h));
}

// =============================================================================
// KNN: warp-per-query, 32 warps (= 32 queries) per 1024-thread block so each
// candidate tile load is amortized over 32 queries (4x less L2 traffic than
// 8-warp blocks). Candidates staged as float4 (x,y,z,|c|^2); |q|^2 folded out
// (constant shift preserves ordering & ties). Lanes own disjoint candidate
// subsets; strict-< insertion + index tie-break in the final register-only
// warp merge reproduce jax.lax.top_k semantics (lower index first on ties).
// =============================================================================
__global__ void __launch_bounds__(1024) knn_kernel(const float* __restrict__ pos)
{
    __shared__ float4 s_c4[1024];        // 16KB
    __shared__ float  s_raw[1024 * 3];   // 12KB

    const int tid   = threadIdx.x;
    const int warp  = tid >> 5;
    const int lane  = tid & 31;
    const int qglob = blockIdx.x * 32 + warp;       // [0, 16384), no batch straddle
    const int b     = qglob >> 13;
    const int qn    = qglob & (NN - 1);
    const float* posb = pos + (size_t)b * NN * 3;

    const float qx2 = -2.0f * posb[qn * 3 + 0];
    const float qy2 = -2.0f * posb[qn * 3 + 1];
    const float qz2 = -2.0f * posb[qn * 3 + 2];

    float bd[8]; int bi[8];
#pragma unroll
    for (int j = 0; j < 8; ++j) { bd[j] = __int_as_float(0x7f800000); bi[j] = 0x7fffffff; }

    for (int tile = 0; tile < NN; tile += 1024) {
        __syncthreads();
        // 1024 positions = 3072 floats = 768 float4 loads
        if (tid < 768)
            ((float4*)s_raw)[tid] = ((const float4*)(posb + (size_t)tile * 3))[tid];
        __syncthreads();
        {
            const float cx = s_raw[tid * 3 + 0];
            const float cy = s_raw[tid * 3 + 1];
            const float cz = s_raw[tid * 3 + 2];
            s_c4[tid] = make_float4(cx, cy, cz, cx * cx + cy * cy + cz * cz);
        }
        __syncthreads();

#pragma unroll 4
        for (int j = 0; j < 32; ++j) {
            const int c = lane + 32 * j;
            const float4 p = s_c4[c];
            // d2 - |q|^2 = |c|^2 - 2 q.c   (same ordering as d2)
            const float t = fmaf(p.x, qx2, fmaf(p.y, qy2, fmaf(p.z, qz2, p.w)));
            if (t < bd[7]) {                       // strict <: equal keeps lower index
                bd[7] = t; bi[7] = tile + c;
#pragma unroll
                for (int u = 7; u > 0; --u) {
                    if (bd[u] < bd[u - 1]) {       // strict: stable on ties
                        float tf = bd[u - 1]; bd[u - 1] = bd[u]; bd[u] = tf;
                        int   ti = bi[u - 1]; bi[u - 1] = bi[u]; bi[u] = ti;
                    }
                }
            }
        }
    }

    // ---- register-only warp merge of 32 sorted 8-lists ----
#pragma unroll
    for (int r = 0; r < 8; ++r) {
        float bv = bd[0]; int bii = bi[0];
#pragma unroll
        for (int o = 16; o; o >>= 1) {
            const float ov = __shfl_xor_sync(0xffffffffu, bv, o);
            const int   oi = __shfl_xor_sync(0xffffffffu, bii, o);
            if (ov < bv || (ov == bv && oi < bii)) { bv = ov; bii = oi; }
        }
        if (lane == 0) g_IDX[(size_t)qglob * 8 + r] = bii;
        if (bi[0] == bii) {                        // winner lane advances its head
#pragma unroll
            for (int u = 0; u < 7; ++u) { bd[u] = bd[u + 1]; bi[u] = bi[u + 1]; }
            bd[7] = __int_as_float(0x7f800000); bi[7] = 0x7fffffff;
        }
    }
}

// =============================================================================
// Conversions: fp32 -> fp16 (A: hi|lo split, B: hi duplicated), extended-K.
// =============================================================================
__global__ void __launch_bounds__(256) conv_x_kernel(const float* __restrict__ x)
{
    const int idx = blockIdx.x * 256 + threadIdx.x;   // [0, MTOT*DD)
    const int row = idx >> 8, k = idx & 255;
    __half h, l;
    split_f16(x[idx], h, l);
    __half* r = g_X2 + (size_t)row * K2_QKV;
    r[k] = h; r[DD + k] = l;                          // [Ah|Al]
}

__global__ void __launch_bounds__(256) conv_wqkv_kernel(const float* __restrict__ Wq,
                                                        const float* __restrict__ Wkv)
{
    const int idx = blockIdx.x * 256 + threadIdx.x;   // [0, NQKV*DD)
    const int n = idx >> 8, k = idx & 255;
    const float v = (n < INNER) ? Wq[(size_t)k * INNER + n]
                                : Wkv[(size_t)k * (2 * INNER) + (n - INNER)];
    const __half h = __float2half(v);
    __half* r = g_WT + (size_t)n * K2_QKV;
    r[k] = h; r[DD + k] = h;                          // [Bh|Bh]
}

__global__ void __launch_bounds__(256) conv_wout_kernel(const float* __restrict__ Wout)
{
    const int idx = blockIdx.x * 256 + threadIdx.x;   // [0, DD*INNER)
    const int n = idx >> 9, k = idx & 511;
    const __half h = __float2half(Wout[(size_t)k * DD + n]);
    __half* r = g_WTO + (size_t)n * K2_OUT;
    r[k] = h; r[INNER + k] = h;                       // [Bh|Bh]
}

// =============================================================================
// fp16 tensor-core GEMM via mma.sync. C[M,N] = A[M,K2] * Bt[N,K2]^T (+bias).
// CTA 128x128, 256 THREADS: 8 warps in 2x4 grid, each m64 x n32.
// K-chunk 64, 3-stage cp.async. 16 warps/SM (4/SMSP) hide LDSM/HMMA latency.
// B uses PLAIN ldmatrix (N-major rows, K contiguous -> .col fragment directly).
// =============================================================================
#define GSTAGES   3
#define GSTAGE_B  32768                       // A 16KB + B 16KB
#define GEMM_SMEM (GSTAGES * GSTAGE_B)        // 96 KB

__device__ __forceinline__ void mma_f16(float* d, const uint32_t* a, const uint32_t* b)
{
    asm volatile(
        "mma.sync.aligned.m16n8k16.row.col.f32.f16.f16.f32 "
        "{%0,%1,%2,%3}, {%4,%5,%6,%7}, {%8,%9}, {%0,%1,%2,%3};"
        : "+f"(d[0]), "+f"(d[1]), "+f"(d[2]), "+f"(d[3])
        : "r"(a[0]), "r"(a[1]), "r"(a[2]), "r"(a[3]), "r"(b[0]), "r"(b[1]));
}

__device__ __forceinline__ void ldsm_x4(uint32_t* r, uint32_t a)
{
    asm volatile("ldmatrix.sync.aligned.m8n8.x4.shared.b16 {%0,%1,%2,%3}, [%4];"
        : "=r"(r[0]), "=r"(r[1]), "=r"(r[2]), "=r"(r[3]) : "r"(a));
}

__global__ void __launch_bounds__(256, 2) gemm_mma_kernel(
    const __half* __restrict__ A,   // [M, K2] row-major
    const __half* __restrict__ Bt,  // [N, K2] row-major (N-major weights)
    float* __restrict__ C, const float* __restrict__ bias,
    int Nglob, int K2)
{
    extern __shared__ char smem[];
    const uint32_t sb = smem_u32(smem);
    const int tid  = threadIdx.x;
    const int warp = tid >> 5, lane = tid & 31;
    const int wm = warp & 1, wn = warp >> 1;          // 2 x 4 warp grid
    const int m0 = blockIdx.y * 128, n0 = blockIdx.x * 128;
    const int nch = K2 >> 6;

    float acc[4][4][4];
#pragma unroll
    for (int i = 0; i < 4; ++i)
#pragma unroll
        for (int j = 0; j < 4; ++j)
#pragma unroll
            for (int t = 0; t < 4; ++t) acc[i][j][t] = 0.0f;

    const int a_row = wm * 64 + (lane & 15);                    // + mi*16
    const int a_k   = (lane >> 4);                              // + 2*ks
    const int b_row = wn * 32 + ((lane & 16) >> 1) + (lane & 7);// + half*16
    const int b_k   = ((lane >> 3) & 1);                        // + 2*ks

    auto load_stage = [&](int s, int kc) {
        const uint32_t st = sb + s * GSTAGE_B;
#pragma unroll
        for (int it = 0; it < 4; ++it) {
            const int idx = it * 256 + tid;
            const int row = idx >> 3, c = idx & 7;
            cp_async16(st + row * 128 + ((c ^ (row & 7)) << 4),
                       A + (size_t)(m0 + row) * K2 + kc * 64 + c * 8);
        }
#pragma unroll
        for (int it = 0; it < 4; ++it) {
            const int idx = it * 256 + tid;
            const int row = idx >> 3, c = idx & 7;
            cp_async16(st + 16384 + row * 128 + ((c ^ (row & 7)) << 4),
                       Bt + (size_t)(n0 + row) * K2 + kc * 64 + c * 8);
        }
    };

    load_stage(0, 0); CP_COMMIT();
    load_stage(1, 1); CP_COMMIT();

    for (int i = 0; i < nch; ++i) {
        if (i + 2 < nch) load_stage((i + 2) % GSTAGES, i + 2);
        CP_COMMIT();
        CP_WAIT2();
        __syncthreads();

        const uint32_t stA = sb + (i % GSTAGES) * GSTAGE_B;
        const uint32_t stB = stA + 16384;

#pragma unroll
        for (int ks = 0; ks < 4; ++ks) {
            uint32_t af[4][4], bf[2][4];
#pragma unroll
            for (int mi = 0; mi < 4; ++mi) {
                const int row = a_row + mi * 16;
                const int kc  = 2 * ks + a_k;
                ldsm_x4(af[mi], stA + row * 128 + ((kc ^ (row & 7)) << 4));
            }
#pragma unroll
            for (int h = 0; h < 2; ++h) {
                const int row = b_row + h * 16;
                const int kc  = 2 * ks + b_k;
                ldsm_x4(bf[h], stB + row * 128 + ((kc ^ (row & 7)) << 4));
            }
#pragma unroll
            for (int mi = 0; mi < 4; ++mi)
#pragma unroll
                for (int nj = 0; nj < 4; ++nj)
                    mma_f16(acc[mi][nj], af[mi], &bf[nj >> 1][(nj & 1) * 2]);
        }
        __syncthreads();
    }

    // epilogue
    const int g = lane >> 2, tg = lane & 3;
#pragma unroll
    for (int mi = 0; mi < 4; ++mi) {
        const int r0 = m0 + wm * 64 + mi * 16 + g;
#pragma unroll
        for (int nj = 0; nj < 4; ++nj) {
            const int col = n0 + wn * 32 + nj * 8 + tg * 2;
            float b0 = 0.0f, b1 = 0.0f;
            if (bias) { b0 = bias[col]; b1 = bias[col + 1]; }
            float2 o0 = make_float2(acc[mi][nj][0] + b0, acc[mi][nj][1] + b1);
            float2 o1 = make_float2(acc[mi][nj][2] + b0, acc[mi][nj][3] + b1);
            *(float2*)&C[(size_t)r0 * Nglob + col]       = o0;
            *(float2*)&C[(size_t)(r0 + 8) * Nglob + col] = o1;
        }
    }
}

// =============================================================================
// Attention: one block per point (8 warps = 8 heads); reads fused QKV,
// writes fp16 split activation [Ah|Al] (feeds the out-proj GEMM).
// =============================================================================
__global__ void __launch_bounds__(256) attn_kernel()
{
    const int point = blockIdx.x;
    const int warp  = threadIdx.x >> 5;
    const int lane  = threadIdx.x & 31;
    const int b     = point >> 13;
    const int baseb = b * NN;

    const int* idxp = g_IDX + (size_t)point * 8;
    const float2 qh = *(const float2*)&g_QKV[(size_t)point * NQKV + warp * DHD + lane * 2];

    float dots[8];
    int   nbs[8];
#pragma unroll
    for (int k = 0; k < 8; ++k) {
        const int nb = idxp[k];
        nbs[k] = nb;
        const float2 kk = *(const float2*)&g_QKV[(size_t)(baseb + nb) * NQKV + INNER + warp * DHD + lane * 2];
        float d = qh.x * kk.x + qh.y * kk.y;
#pragma unroll
        for (int o = 16; o; o >>= 1) d += __shfl_xor_sync(0xffffffffu, d, o);
        dots[k] = d * 0.125f;
    }

    float m = dots[0];
#pragma unroll
    for (int k = 1; k < 8; ++k) m = fmaxf(m, dots[k]);
    float e[8], s = 0.0f;
#pragma unroll
    for (int k = 0; k < 8; ++k) { e[k] = expf(dots[k] - m); s += e[k]; }
    const float inv = 1.0f / s;

    float2 acc = make_float2(0.0f, 0.0f);
#pragma unroll
    for (int k = 0; k < 8; ++k) {
        const float2 vv = *(const float2*)&g_QKV[(size_t)(baseb + nbs[k]) * NQKV + 2 * INNER + warp * DHD + lane * 2];
        const float a = e[k] * inv;
        acc.x = fmaf(a, vv.x, acc.x);
        acc.y = fmaf(a, vv.y, acc.y);
    }

    __half hx, lx, hy, ly;
    split_f16(acc.x, hx, lx);
    split_f16(acc.y, hy, ly);
    __half2 hp; hp.x = hx; hp.y = hy;
    __half2 lp; lp.x = lx; lp.y = ly;
    __half* r = g_AT2 + (size_t)point * K2_OUT + warp * DHD + lane * 2;
    *(__half2*)(r)         = hp;   // Ah
    *(__half2*)(r + INNER) = lp;   // Al
}

// =============================================================================
extern "C" void kernel_launch(void* const* d_in, const int* in_sizes, int n_in,
                              void* d_out, int out_size)
{
    const float* x    = (const float*)d_in[0];
    const float* pos  = (const float*)d_in[1];
    const float* Wq   = (const float*)d_in[2];
    const float* Wkv  = (const float*)d_in[3];
    const float* Wout = (const float*)d_in[4];
    const float* bout = (const float*)d_in[5];
    float* out = (float*)d_out;

    cudaFuncSetAttribute(gemm_mma_kernel,
                         cudaFuncAttributeMaxDynamicSharedMemorySize, GEMM_SMEM);

    __half *pX2, *pWT, *pWTO, *pAT2;
    float *pQKV;
    cudaGetSymbolAddress((void**)&pX2,  g_X2);
    cudaGetSymbolAddress((void**)&pWT,  g_WT);
    cudaGetSymbolAddress((void**)&pWTO, g_WTO);
    cudaGetSymbolAddress((void**)&pQKV, g_QKV);
    cudaGetSymbolAddress((void**)&pAT2, g_AT2);

    // Launch order puts KNN at the deterministically-profiled 4th slot.
    // 1-3) conversions
    conv_x_kernel<<<MTOT * DD / 256, 256>>>(x);
    conv_wqkv_kernel<<<NQKV * DD / 256, 256>>>(Wq, Wkv);
    conv_wout_kernel<<<DD * INNER / 256, 256>>>(Wout);

    // 4) KNN  (profiled this round)
    knn_kernel<<<MTOT / 32, 1024>>>(pos);

    // 5) fused QKV = x @ [Wq|Wkv]  (tensor cores, 2-term fp16 as K'=512)
    gemm_mma_kernel<<<dim3(NQKV / 128, MTOT / 128), 256, GEMM_SMEM>>>(
        pX2, pWT, pQKV, nullptr, NQKV, K2_QKV);

    // 6) neighbor attention (writes fp16 split activation)
    attn_kernel<<<MTOT, 256>>>();

    // 7) out = ATT @ Wout + bout   (tensor cores, 2-term fp16 as K'=1024)
    gemm_mma_kernel<<<dim3(DD / 128, MTOT / 128), 256, GEMM_SMEM>>>(
        pAT2, pWTO, out, bout, DD, K2_OUT);
}

// round 9
// speedup vs baseline: 1.6318x; 1.6318x over previous
#include <cuda_runtime.h>
#include <cuda_fp16.h>
#include <math.h>
#include <stdint.h>

// Problem constants
#define BB    2
#define NN    8192
#define DD    256
#define HH    8
#define DHD   64
#define KNB   8
#define INNER 512
#define MTOT  (BB*NN)        // 16384
#define NQKV  (3*INNER)      // 1536 = Q | K | V

// 2-term fp16 split as extended-K plain GEMM:
//   A2 = [Ah | Al], B2 = [Bh | Bh]  ->  C = A*Bh (only fp16 rounding of B)
#define K2_QKV (2*DD)        // 512
#define K2_OUT (2*INNER)     // 1024

// KNN slicing
#define NSLICE 4
#define SLICE  (NN / NSLICE)   // 2048 candidates per slice

// ---------------- static device scratch ----------------
__device__ __half g_X2 [(size_t)MTOT * K2_QKV];     // 16.8 MB
__device__ __half g_WT [(size_t)NQKV * K2_QKV];     // 1.5 MB (N-major)
__device__ __half g_WTO[(size_t)DD * K2_OUT];       // 0.5 MB (N-major)
__device__ float  g_QKV[(size_t)MTOT * NQKV];       // 100 MB
__device__ __half g_AT2[(size_t)MTOT * K2_OUT];     // 33.6 MB
__device__ int    g_IDX[(size_t)MTOT * KNB];
__device__ float  g_PD [(size_t)MTOT * NSLICE * KNB];   // partial top-8 dists
__device__ int    g_PI [(size_t)MTOT * NSLICE * KNB];   // partial top-8 idxs

__device__ __forceinline__ uint32_t smem_u32(const void* p) {
    uint32_t a;
    asm("{ .reg .u64 t; cvta.to.shared.u64 t, %1; cvt.u32.u64 %0, t; }" : "=r"(a) : "l"(p));
    return a;
}
__device__ __forceinline__ void cp_async16(uint32_t s, const void* g) {
    asm volatile("cp.async.cg.shared.global [%0], [%1], 16;" :: "r"(s), "l"(g));
}
#define CP_COMMIT()  asm volatile("cp.async.commit_group;" ::: "memory")
#define CP_WAIT2()   asm volatile("cp.async.wait_group 2;" ::: "memory")

__device__ __forceinline__ void split_f16(float v, __half& h, __half& l) {
    h = __float2half(v);
    l = __float2half(v - __half2float(h));
}

// =============================================================================
// KNN scan: LANE-PER-QUERY over a candidate SLICE. Each thread owns one query
// and scans SLICE candidates broadcast from smem (same address all lanes ->
// 16B broadcast). Warp covers 32 different queries, so divergent insertion
// steps decay as 256/j instead of being 100% (warp-per-query failure mode).
// Strict-< in-order insertion => per-slice sorted top-8, lower index on ties.
// grid = (MTOT/256, NSLICE), block = 256.
// =============================================================================
__global__ void __launch_bounds__(256) knn_scan_kernel(const float* __restrict__ pos)
{
    __shared__ float4 s_c4[1024];        // 16KB
    __shared__ float  s_raw[1024 * 3];   // 12KB

    const int tid   = threadIdx.x;
    const int q     = blockIdx.x * 256 + tid;       // [0, 16384); block never straddles batch
    const int slice = blockIdx.y;
    const int b     = q >> 13;
    const int qn    = q & (NN - 1);
    const float* posb = pos + (size_t)b * NN * 3;

    const float qx2 = -2.0f * posb[qn * 3 + 0];
    const float qy2 = -2.0f * posb[qn * 3 + 1];
    const float qz2 = -2.0f * posb[qn * 3 + 2];

    float bd[8]; int bi[8];
#pragma unroll
    for (int j = 0; j < 8; ++j) { bd[j] = __int_as_float(0x7f800000); bi[j] = 0x7fffffff; }

    for (int t = 0; t < SLICE / 1024; ++t) {
        const int cbase = slice * SLICE + t * 1024;
        __syncthreads();
        // stage 1024 positions = 768 float4
        {
            const float4* src = (const float4*)(posb + (size_t)cbase * 3);
            float4*       dst = (float4*)s_raw;
#pragma unroll
            for (int i = 0; i < 3; ++i)
                dst[tid + 256 * i] = src[tid + 256 * i];
        }
        __syncthreads();
#pragma unroll
        for (int i = 0; i < 4; ++i) {
            const int c = tid + 256 * i;
            const float cx = s_raw[c * 3 + 0];
            const float cy = s_raw[c * 3 + 1];
            const float cz = s_raw[c * 3 + 2];
            s_c4[c] = make_float4(cx, cy, cz, cx * cx + cy * cy + cz * cz);
        }
        __syncthreads();

#pragma unroll 4
        for (int c = 0; c < 1024; ++c) {
            const float4 p = s_c4[c];                       // broadcast LDS
            // d2 - |q|^2 = |c|^2 - 2 q.c (constant shift: same ordering & ties)
            const float tt = fmaf(p.x, qx2, fmaf(p.y, qy2, fmaf(p.z, qz2, p.w)));
            if (tt < bd[7]) {                               // strict <
                bd[7] = tt; bi[7] = cbase + c;
#pragma unroll
                for (int u = 7; u > 0; --u) {
                    if (bd[u] < bd[u - 1]) {                // stable on ties
                        float tf = bd[u - 1]; bd[u - 1] = bd[u]; bd[u] = tf;
                        int   ti = bi[u - 1]; bi[u - 1] = bi[u]; bi[u] = ti;
                    }
                }
            }
        }
    }

    float* pd = g_PD + ((size_t)q * NSLICE + slice) * 8;
    int*   pi = g_PI + ((size_t)q * NSLICE + slice) * 8;
#pragma unroll
    for (int j = 0; j < 8; ++j) { pd[j] = bd[j]; pi[j] = bi[j]; }
}

// =============================================================================
// KNN merge: per query, 4-way merge of sorted 8-lists with (dist, idx)
// tie-break (lower index wins) — exact jax.lax.top_k order.
// =============================================================================
__global__ void __launch_bounds__(256) knn_merge_kernel()
{
    const int q = blockIdx.x * 256 + threadIdx.x;
    const float* pd = g_PD + (size_t)q * 32;
    const int*   pi = g_PI + (size_t)q * 32;
    const float INF = __int_as_float(0x7f800000);

    int p0 = 0, p1 = 0, p2 = 0, p3 = 0;
    int out[8];
#pragma unroll
    for (int r = 0; r < 8; ++r) {
        const float d0 = (p0 < 8) ? pd[p0]      : INF;
        const float d1 = (p1 < 8) ? pd[8 + p1]  : INF;
        const float d2 = (p2 < 8) ? pd[16 + p2] : INF;
        const float d3 = (p3 < 8) ? pd[24 + p3] : INF;
        const int   i0 = (p0 < 8) ? pi[p0]      : 0x7fffffff;
        const int   i1 = (p1 < 8) ? pi[8 + p1]  : 0x7fffffff;
        const int   i2 = (p2 < 8) ? pi[16 + p2] : 0x7fffffff;
        const int   i3 = (p3 < 8) ? pi[24 + p3] : 0x7fffffff;

        float bdv = d0; int biv = i0; int sel = 0;
        if (d1 < bdv || (d1 == bdv && i1 < biv)) { bdv = d1; biv = i1; sel = 1; }
        if (d2 < bdv || (d2 == bdv && i2 < biv)) { bdv = d2; biv = i2; sel = 2; }
        if (d3 < bdv || (d3 == bdv && i3 < biv)) { bdv = d3; biv = i3; sel = 3; }
        out[r] = biv;
        if      (sel == 0) ++p0;
        else if (sel == 1) ++p1;
        else if (sel == 2) ++p2;
        else               ++p3;
    }
    *(int4*)&g_IDX[(size_t)q * 8]     = make_int4(out[0], out[1], out[2], out[3]);
    *(int4*)&g_IDX[(size_t)q * 8 + 4] = make_int4(out[4], out[5], out[6], out[7]);
}

// =============================================================================
// Conversions: fp32 -> fp16 (A: hi|lo split, B: hi duplicated), extended-K.
// =============================================================================
__global__ void __launch_bounds__(256) conv_x_kernel(const float* __restrict__ x)
{
    const int idx = blockIdx.x * 256 + threadIdx.x;   // [0, MTOT*DD)
    const int row = idx >> 8, k = idx & 255;
    __half h, l;
    split_f16(x[idx], h, l);
    __half* r = g_X2 + (size_t)row * K2_QKV;
    r[k] = h; r[DD + k] = l;                          // [Ah|Al]
}

__global__ void __launch_bounds__(256) conv_wqkv_kernel(const float* __restrict__ Wq,
                                                        const float* __restrict__ Wkv)
{
    const int idx = blockIdx.x * 256 + threadIdx.x;   // [0, NQKV*DD)
    const int n = idx >> 8, k = idx & 255;
    const float v = (n < INNER) ? Wq[(size_t)k * INNER + n]
                                : Wkv[(size_t)k * (2 * INNER) + (n - INNER)];
    const __half h = __float2half(v);
    __half* r = g_WT + (size_t)n * K2_QKV;
    r[k] = h; r[DD + k] = h;                          // [Bh|Bh]
}

__global__ void __launch_bounds__(256) conv_wout_kernel(const float* __restrict__ Wout)
{
    const int idx = blockIdx.x * 256 + threadIdx.x;   // [0, DD*INNER)
    const int n = idx >> 9, k = idx & 511;
    const __half h = __float2half(Wout[(size_t)k * DD + n]);
    __half* r = g_WTO + (size_t)n * K2_OUT;
    r[k] = h; r[INNER + k] = h;                       // [Bh|Bh]
}

// =============================================================================
// fp16 tensor-core GEMM via mma.sync (unchanged from round 7/8 — measured
// 82.5us @ tensor 51% on QKV). CTA 128x128, 256 thr (2x4 warps of m64 x n32),
// K-chunk 64, 3-stage cp.async, PLAIN ldmatrix for N-major B.
// =============================================================================
#define GSTAGES   3
#define GSTAGE_B  32768                       // A 16KB + B 16KB
#define GEMM_SMEM (GSTAGES * GSTAGE_B)        // 96 KB

__device__ __forceinline__ void mma_f16(float* d, const uint32_t* a, const uint32_t* b)
{
    asm volatile(
        "mma.sync.aligned.m16n8k16.row.col.f32.f16.f16.f32 "
        "{%0,%1,%2,%3}, {%4,%5,%6,%7}, {%8,%9}, {%0,%1,%2,%3};"
        : "+f"(d[0]), "+f"(d[1]), "+f"(d[2]), "+f"(d[3])
        : "r"(a[0]), "r"(a[1]), "r"(a[2]), "r"(a[3]), "r"(b[0]), "r"(b[1]));
}

__device__ __forceinline__ void ldsm_x4(uint32_t* r, uint32_t a)
{
    asm volatile("ldmatrix.sync.aligned.m8n8.x4.shared.b16 {%0,%1,%2,%3}, [%4];"
        : "=r"(r[0]), "=r"(r[1]), "=r"(r[2]), "=r"(r[3]) : "r"(a));
}

__global__ void __launch_bounds__(256, 2) gemm_mma_kernel(
    const __half* __restrict__ A,   // [M, K2] row-major
    const __half* __restrict__ Bt,  // [N, K2] row-major (N-major weights)
    float* __restrict__ C, const float* __restrict__ bias,
    int Nglob, int K2)
{
    extern __shared__ char smem[];
    const uint32_t sb = smem_u32(smem);
    const int tid  = threadIdx.x;
    const int warp = tid >> 5, lane = tid & 31;
    const int wm = warp & 1, wn = warp >> 1;          // 2 x 4 warp grid
    const int m0 = blockIdx.y * 128, n0 = blockIdx.x * 128;
    const int nch = K2 >> 6;

    float acc[4][4][4];
#pragma unroll
    for (int i = 0; i < 4; ++i)
#pragma unroll
        for (int j = 0; j < 4; ++j)
#pragma unroll
            for (int t = 0; t < 4; ++t) acc[i][j][t] = 0.0f;

    const int a_row = wm * 64 + (lane & 15);                    // + mi*16
    const int a_k   = (lane >> 4);                              // + 2*ks
    const int b_row = wn * 32 + ((lane & 16) >> 1) + (lane & 7);// + half*16
    const int b_k   = ((lane >> 3) & 1);                        // + 2*ks

    auto load_stage = [&](int s, int kc) {
        const uint32_t st = sb + s * GSTAGE_B;
#pragma unroll
        for (int it = 0; it < 4; ++it) {
            const int idx = it * 256 + tid;
            const int row = idx >> 3, c = idx & 7;
            cp_async16(st + row * 128 + ((c ^ (row & 7)) << 4),
                       A + (size_t)(m0 + row) * K2 + kc * 64 + c * 8);
        }
#pragma unroll
        for (int it = 0; it < 4; ++it) {
            const int idx = it * 256 + tid;
            const int row = idx >> 3, c = idx & 7;
            cp_async16(st + 16384 + row * 128 + ((c ^ (row & 7)) << 4),
                       Bt + (size_t)(n0 + row) * K2 + kc * 64 + c * 8);
        }
    };

    load_stage(0, 0); CP_COMMIT();
    load_stage(1, 1); CP_COMMIT();

    for (int i = 0; i < nch; ++i) {
        if (i + 2 < nch) load_stage((i + 2) % GSTAGES, i + 2);
        CP_COMMIT();
        CP_WAIT2();
        __syncthreads();

        const uint32_t stA = sb + (i % GSTAGES) * GSTAGE_B;
        const uint32_t stB = stA + 16384;

#pragma unroll
        for (int ks = 0; ks < 4; ++ks) {
            uint32_t af[4][4], bf[2][4];
#pragma unroll
            for (int mi = 0; mi < 4; ++mi) {
                const int row = a_row + mi * 16;
                const int kc  = 2 * ks + a_k;
                ldsm_x4(af[mi], stA + row * 128 + ((kc ^ (row & 7)) << 4));
            }
#pragma unroll
            for (int h = 0; h < 2; ++h) {
                const int row = b_row + h * 16;
                const int kc  = 2 * ks + b_k;
                ldsm_x4(bf[h], stB + row * 128 + ((kc ^ (row & 7)) << 4));
            }
#pragma unroll
            for (int mi = 0; mi < 4; ++mi)
#pragma unroll
                for (int nj = 0; nj < 4; ++nj)
                    mma_f16(acc[mi][nj], af[mi], &bf[nj >> 1][(nj & 1) * 2]);
        }
        __syncthreads();
    }

    // epilogue
    const int g = lane >> 2, tg = lane & 3;
#pragma unroll
    for (int mi = 0; mi < 4; ++mi) {
        const int r0 = m0 + wm * 64 + mi * 16 + g;
#pragma unroll
        for (int nj = 0; nj < 4; ++nj) {
            const int col = n0 + wn * 32 + nj * 8 + tg * 2;
            float b0 = 0.0f, b1 = 0.0f;
            if (bias) { b0 = bias[col]; b1 = bias[col + 1]; }
            float2 o0 = make_float2(acc[mi][nj][0] + b0, acc[mi][nj][1] + b1);
            float2 o1 = make_float2(acc[mi][nj][2] + b0, acc[mi][nj][3] + b1);
            *(float2*)&C[(size_t)r0 * Nglob + col]       = o0;
            *(float2*)&C[(size_t)(r0 + 8) * Nglob + col] = o1;
        }
    }
}

// =============================================================================
// Attention: one block per point (8 warps = 8 heads); reads fused QKV,
// writes fp16 split activation [Ah|Al] (feeds the out-proj GEMM).
// =============================================================================
__global__ void __launch_bounds__(256) attn_kernel()
{
    const int point = blockIdx.x;
    const int warp  = threadIdx.x >> 5;
    const int lane  = threadIdx.x & 31;
    const int b     = point >> 13;
    const int baseb = b * NN;

    const int* idxp = g_IDX + (size_t)point * 8;
    const float2 qh = *(const float2*)&g_QKV[(size_t)point * NQKV + warp * DHD + lane * 2];

    float dots[8];
    int   nbs[8];
#pragma unroll
    for (int k = 0; k < 8; ++k) {
        const int nb = idxp[k];
        nbs[k] = nb;
        const float2 kk = *(const float2*)&g_QKV[(size_t)(baseb + nb) * NQKV + INNER + warp * DHD + lane * 2];
        float d = qh.x * kk.x + qh.y * kk.y;
#pragma unroll
        for (int o = 16; o; o >>= 1) d += __shfl_xor_sync(0xffffffffu, d, o);
        dots[k] = d * 0.125f;
    }

    float m = dots[0];
#pragma unroll
    for (int k = 1; k < 8; ++k) m = fmaxf(m, dots[k]);
    float e[8], s = 0.0f;
#pragma unroll
    for (int k = 0; k < 8; ++k) { e[k] = expf(dots[k] - m); s += e[k]; }
    const float inv = 1.0f / s;

    float2 acc = make_float2(0.0f, 0.0f);
#pragma unroll
    for (int k = 0; k < 8; ++k) {
        const float2 vv = *(const float2*)&g_QKV[(size_t)(baseb + nbs[k]) * NQKV + 2 * INNER + warp * DHD + lane * 2];
        const float a = e[k] * inv;
        acc.x = fmaf(a, vv.x, acc.x);
        acc.y = fmaf(a, vv.y, acc.y);
    }

    __half hx, lx, hy, ly;
    split_f16(acc.x, hx, lx);
    split_f16(acc.y, hy, ly);
    __half2 hp; hp.x = hx; hp.y = hy;
    __half2 lp; lp.x = lx; lp.y = ly;
    __half* r = g_AT2 + (size_t)point * K2_OUT + warp * DHD + lane * 2;
    *(__half2*)(r)         = hp;   // Ah
    *(__half2*)(r + INNER) = lp;   // Al
}

// =============================================================================
extern "C" void kernel_launch(void* const* d_in, const int* in_sizes, int n_in,
                              void* d_out, int out_size)
{
    const float* x    = (const float*)d_in[0];
    const float* pos  = (const float*)d_in[1];
    const float* Wq   = (const float*)d_in[2];
    const float* Wkv  = (const float*)d_in[3];
    const float* Wout = (const float*)d_in[4];
    const float* bout = (const float*)d_in[5];
    float* out = (float*)d_out;

    cudaFuncSetAttribute(gemm_mma_kernel,
                         cudaFuncAttributeMaxDynamicSharedMemorySize, GEMM_SMEM);

    __half *pX2, *pWT, *pWTO, *pAT2;
    float *pQKV;
    cudaGetSymbolAddress((void**)&pX2,  g_X2);
    cudaGetSymbolAddress((void**)&pWT,  g_WT);
    cudaGetSymbolAddress((void**)&pWTO, g_WTO);
    cudaGetSymbolAddress((void**)&pQKV, g_QKV);
    cudaGetSymbolAddress((void**)&pAT2, g_AT2);

    // knn_scan at the deterministically-profiled 4th launch slot.
    // 1-3) conversions
    conv_x_kernel<<<MTOT * DD / 256, 256>>>(x);
    conv_wqkv_kernel<<<NQKV * DD / 256, 256>>>(Wq, Wkv);
    conv_wout_kernel<<<DD * INNER / 256, 256>>>(Wout);

    // 4) KNN scan (lane-per-query, 4 slices) — profiled this round
    knn_scan_kernel<<<dim3(MTOT / 256, NSLICE), 256>>>(pos);

    // 5) KNN merge (4-way sorted merge, tie-break on index)
    knn_merge_kernel<<<MTOT / 256, 256>>>();

    // 6) fused QKV = x @ [Wq|Wkv]  (tensor cores, 2-term fp16 as K'=512)
    gemm_mma_kernel<<<dim3(NQKV / 128, MTOT / 128), 256, GEMM_SMEM>>>(
        pX2, pWT, pQKV, nullptr, NQKV, K2_QKV);

    // 7) neighbor attention (writes fp16 split activation)
    attn_kernel<<<MTOT, 256>>>();

    // 8) out = ATT @ Wout + bout   (tensor cores, 2-term fp16 as K'=1024)
    gemm_mma_kernel<<<dim3(DD / 128, MTOT / 128), 256, GEMM_SMEM>>>(
        pAT2, pWTO, out, bout, DD, K2_OUT);
}

// round 10
// speedup vs baseline: 1.7442x; 1.0689x over previous
#include <cuda_runtime.h>
#include <cuda_fp16.h>
#include <math.h>
#include <stdint.h>

// Problem constants
#define BB    2
#define NN    8192
#define DD    256
#define HH    8
#define DHD   64
#define KNB   8
#define INNER 512
#define MTOT  (BB*NN)        // 16384
#define NQKV  (3*INNER)      // 1536 = Q | K | V

// 2-term fp16 split as extended-K plain GEMM
#define K2_QKV (2*DD)        // 512
#define K2_OUT (2*INNER)     // 1024

// KNN slicing
#define NSLICE 8
#define SLICE  (NN / NSLICE)   // 1024 candidates per slice
#define KCAP   16              // per-thread append buffer entries

// ---------------- static device scratch ----------------
__device__ __half g_X2 [(size_t)MTOT * K2_QKV];
__device__ __half g_WT [(size_t)NQKV * K2_QKV];
__device__ __half g_WTO[(size_t)DD * K2_OUT];
__device__ float  g_QKV[(size_t)MTOT * NQKV];
__device__ __half g_AT2[(size_t)MTOT * K2_OUT];
__device__ int    g_IDX[(size_t)MTOT * KNB];
__device__ float  g_PD [(size_t)MTOT * NSLICE * KNB];   // partial top-8 dists
__device__ int    g_PI [(size_t)MTOT * NSLICE * KNB];   // partial top-8 idxs

__device__ __forceinline__ uint32_t smem_u32(const void* p) {
    uint32_t a;
    asm("{ .reg .u64 t; cvta.to.shared.u64 t, %1; cvt.u32.u64 %0, t; }" : "=r"(a) : "l"(p));
    return a;
}
__device__ __forceinline__ void cp_async16(uint32_t s, const void* g) {
    asm volatile("cp.async.cg.shared.global [%0], [%1], 16;" :: "r"(s), "l"(g));
}
#define CP_COMMIT()  asm volatile("cp.async.commit_group;" ::: "memory")
#define CP_WAIT2()   asm volatile("cp.async.wait_group 2;" ::: "memory")

__device__ __forceinline__ void split_f16(float v, __half& h, __half& l) {
    h = __float2half(v);
    l = __float2half(v - __half2float(h));
}

// =============================================================================
// KNN scan: lane-per-query, BRANCHLESS inner loop. Candidates (x,y,z,|c|^2)
// broadcast from smem; passing candidates appended to a per-thread smem buffer
// via predicated @p st.shared (no BSSY). Threshold = current 8th-best, updated
// only at rare warp-collective flush events. Lazy threshold only over-appends,
// never misses a true top-8 member. Flush processes entries in append (=index)
// order with strict-< insertion -> exact jax.lax.top_k tie semantics.
// grid = (MTOT/256, NSLICE), block = 256. Dynamic smem 60KB.
// =============================================================================
#define KNN_SMEM (16384 + 12288 + 256 * KCAP * 8)   // s_c4 + s_raw + buffer

__global__ void __launch_bounds__(256) knn_scan_kernel(const float* __restrict__ pos)
{
    extern __shared__ char sm[];
    float4* s_c4  = (float4*)sm;                         // 16KB
    float*  s_raw = (float*)(sm + 16384);                // 12KB
    float2* s_buf = (float2*)(sm + 16384 + 12288);       // 32KB: [entry][tid]

    const int tid   = threadIdx.x;
    const int q     = blockIdx.x * 256 + tid;            // no batch straddle
    const int slice = blockIdx.y;
    const int b     = q >> 13;
    const int qn    = q & (NN - 1);
    const float* posb = pos + (size_t)b * NN * 3;

    const float qx2 = -2.0f * posb[qn * 3 + 0];
    const float qy2 = -2.0f * posb[qn * 3 + 1];
    const float qz2 = -2.0f * posb[qn * 3 + 2];

    // stage this slice's 1024 positions (3072 floats = 768 float4)
    {
        const float4* src = (const float4*)(posb + (size_t)slice * SLICE * 3);
#pragma unroll
        for (int i = 0; i < 3; ++i)
            ((float4*)s_raw)[tid + 256 * i] = src[tid + 256 * i];
    }
    __syncthreads();
#pragma unroll
    for (int i = 0; i < 4; ++i) {
        const int c = tid + 256 * i;
        const float cx = s_raw[c * 3 + 0];
        const float cy = s_raw[c * 3 + 1];
        const float cz = s_raw[c * 3 + 2];
        s_c4[c] = make_float4(cx, cy, cz, cx * cx + cy * cy + cz * cz);
    }
    __syncthreads();

    const float INF = __int_as_float(0x7f800000);
    float bd[8]; int bi[8];
#pragma unroll
    for (int j = 0; j < 8; ++j) { bd[j] = INF; bi[j] = 0x7fffffff; }
    float thr = INF;
    int count = 0;
    const int cbase = slice * SLICE;
    const uint32_t sbuf_tid = smem_u32(s_buf) + tid * 8;   // + count*2048

    // flush: drain buffers of ALL lanes together (rare, warp-uniform entry)
    auto flush = [&]() {
        int mx = count;
#pragma unroll
        for (int o = 16; o; o >>= 1) mx = max(mx, __shfl_xor_sync(0xffffffffu, mx, o));
        for (int k = 0; k < mx; ++k) {
            const float2 e = s_buf[k * 256 + tid];
            if (k < count && e.x < bd[7]) {
                bd[7] = e.x; bi[7] = __float_as_int(e.y);
#pragma unroll
                for (int u = 7; u > 0; --u) {
                    if (bd[u] < bd[u - 1]) {            // strict: stable on ties
                        float tf = bd[u - 1]; bd[u - 1] = bd[u]; bd[u] = tf;
                        int   ti = bi[u - 1]; bi[u - 1] = bi[u]; bi[u] = ti;
                    }
                }
            }
        }
        thr = bd[7];
        count = 0;
    };

    for (int c0 = 0; c0 < SLICE; c0 += 4) {
#pragma unroll
        for (int u = 0; u < 4; ++u) {
            const int c = c0 + u;
            const float4 p = s_c4[c];                    // broadcast LDS
            const float t = fmaf(p.x, qx2, fmaf(p.y, qy2, fmaf(p.z, qz2, p.w)));
            // predicated append (no branch, no BSSY): store only if t < thr
            const uint32_t addr = sbuf_tid + ((uint32_t)count << 11);
            asm volatile(
                "{\n\t.reg .pred p;\n\t"
                "setp.lt.f32 p, %1, %2;\n\t"
                "@p st.shared.v2.f32 [%0], {%1, %3};\n\t}"
                :: "r"(addr), "f"(t), "f"(thr),
                   "f"(__int_as_float(cbase + c)) : "memory");
            count += (t < thr) ? 1 : 0;
        }
        if (__ballot_sync(0xffffffffu, count >= KCAP - 4))   // warp-uniform
            flush();
    }
    flush();

    float* pd = g_PD + ((size_t)q * NSLICE + slice) * 8;
    int*   pi = g_PI + ((size_t)q * NSLICE + slice) * 8;
#pragma unroll
    for (int j = 0; j < 8; ++j) { pd[j] = bd[j]; pi[j] = bi[j]; }
}

// =============================================================================
// KNN merge: per query, 8-way merge of sorted 8-lists with (dist, idx)
// tie-break (lower index wins) — exact jax.lax.top_k order.
// =============================================================================
__global__ void __launch_bounds__(256) knn_merge_kernel()
{
    const int q = blockIdx.x * 256 + threadIdx.x;
    const float* pd = g_PD + (size_t)q * (NSLICE * 8);
    const int*   pi = g_PI + (size_t)q * (NSLICE * 8);
    const float INF = __int_as_float(0x7f800000);

    float hd[NSLICE]; int hi_[NSLICE]; int pp[NSLICE];
#pragma unroll
    for (int s = 0; s < NSLICE; ++s) {
        hd[s] = pd[s * 8]; hi_[s] = pi[s * 8]; pp[s] = 0;
    }

    int out[8];
#pragma unroll
    for (int r = 0; r < 8; ++r) {
        float bdv = hd[0]; int biv = hi_[0]; int sel = 0;
#pragma unroll
        for (int s = 1; s < NSLICE; ++s)
            if (hd[s] < bdv || (hd[s] == bdv && hi_[s] < biv)) {
                bdv = hd[s]; biv = hi_[s]; sel = s;
            }
        out[r] = biv;
#pragma unroll
        for (int s = 0; s < NSLICE; ++s)
            if (sel == s) {
                ++pp[s];
                const bool ok = pp[s] < 8;
                hd[s]  = ok ? pd[s * 8 + pp[s]] : INF;
                hi_[s] = ok ? pi[s * 8 + pp[s]] : 0x7fffffff;
            }
    }
    *(int4*)&g_IDX[(size_t)q * 8]     = make_int4(out[0], out[1], out[2], out[3]);
    *(int4*)&g_IDX[(size_t)q * 8 + 4] = make_int4(out[4], out[5], out[6], out[7]);
}

// =============================================================================
// Conversions: fp32 -> fp16 (A: hi|lo split, B: hi duplicated), extended-K.
// =============================================================================
__global__ void __launch_bounds__(256) conv_x_kernel(const float* __restrict__ x)
{
    const int idx = blockIdx.x * 256 + threadIdx.x;
    const int row = idx >> 8, k = idx & 255;
    __half h, l;
    split_f16(x[idx], h, l);
    __half* r = g_X2 + (size_t)row * K2_QKV;
    r[k] = h; r[DD + k] = l;
}

__global__ void __launch_bounds__(256) conv_wqkv_kernel(const float* __restrict__ Wq,
                                                        const float* __restrict__ Wkv)
{
    const int idx = blockIdx.x * 256 + threadIdx.x;
    const int n = idx >> 8, k = idx & 255;
    const float v = (n < INNER) ? Wq[(size_t)k * INNER + n]
                                : Wkv[(size_t)k * (2 * INNER) + (n - INNER)];
    const __half h = __float2half(v);
    __half* r = g_WT + (size_t)n * K2_QKV;
    r[k] = h; r[DD + k] = h;
}

__global__ void __launch_bounds__(256) conv_wout_kernel(const float* __restrict__ Wout)
{
    const int idx = blockIdx.x * 256 + threadIdx.x;
    const int n = idx >> 9, k = idx & 511;
    const __half h = __float2half(Wout[(size_t)k * DD + n]);
    __half* r = g_WTO + (size_t)n * K2_OUT;
    r[k] = h; r[INNER + k] = h;
}

// =============================================================================
// fp16 tensor-core GEMM via mma.sync (unchanged — 82.5us @ tensor 51% on QKV).
// =============================================================================
#define GSTAGES   3
#define GSTAGE_B  32768
#define GEMM_SMEM (GSTAGES * GSTAGE_B)        // 96 KB

__device__ __forceinline__ void mma_f16(float* d, const uint32_t* a, const uint32_t* b)
{
    asm volatile(
        "mma.sync.aligned.m16n8k16.row.col.f32.f16.f16.f32 "
        "{%0,%1,%2,%3}, {%4,%5,%6,%7}, {%8,%9}, {%0,%1,%2,%3};"
        : "+f"(d[0]), "+f"(d[1]), "+f"(d[2]), "+f"(d[3])
        : "r"(a[0]), "r"(a[1]), "r"(a[2]), "r"(a[3]), "r"(b[0]), "r"(b[1]));
}

__device__ __forceinline__ void ldsm_x4(uint32_t* r, uint32_t a)
{
    asm volatile("ldmatrix.sync.aligned.m8n8.x4.shared.b16 {%0,%1,%2,%3}, [%4];"
        : "=r"(r[0]), "=r"(r[1]), "=r"(r[2]), "=r"(r[3]) : "r"(a));
}

__global__ void __launch_bounds__(256, 2) gemm_mma_kernel(
    const __half* __restrict__ A,
    const __half* __restrict__ Bt,
    float* __restrict__ C, const float* __restrict__ bias,
    int Nglob, int K2)
{
    extern __shared__ char smem[];
    const uint32_t sb = smem_u32(smem);
    const int tid  = threadIdx.x;
    const int warp = tid >> 5, lane = tid & 31;
    const int wm = warp & 1, wn = warp >> 1;
    const int m0 = blockIdx.y * 128, n0 = blockIdx.x * 128;
    const int nch = K2 >> 6;

    float acc[4][4][4];
#pragma unroll
    for (int i = 0; i < 4; ++i)
#pragma unroll
        for (int j = 0; j < 4; ++j)
#pragma unroll
            for (int t = 0; t < 4; ++t) acc[i][j][t] = 0.0f;

    const int a_row = wm * 64 + (lane & 15);
    const int a_k   = (lane >> 4);
    const int b_row = wn * 32 + ((lane & 16) >> 1) + (lane & 7);
    const int b_k   = ((lane >> 3) & 1);

    auto load_stage = [&](int s, int kc) {
        const uint32_t st = sb + s * GSTAGE_B;
#pragma unroll
        for (int it = 0; it < 4; ++it) {
            const int idx = it * 256 + tid;
            const int row = idx >> 3, c = idx & 7;
            cp_async16(st + row * 128 + ((c ^ (row & 7)) << 4),
                       A + (size_t)(m0 + row) * K2 + kc * 64 + c * 8);
        }
#pragma unroll
        for (int it = 0; it < 4; ++it) {
            const int idx = it * 256 + tid;
            const int row = idx >> 3, c = idx & 7;
            cp_async16(st + 16384 + row * 128 + ((c ^ (row & 7)) << 4),
                       Bt + (size_t)(n0 + row) * K2 + kc * 64 + c * 8);
        }
    };

    load_stage(0, 0); CP_COMMIT();
    load_stage(1, 1); CP_COMMIT();

    for (int i = 0; i < nch; ++i) {
        if (i + 2 < nch) load_stage((i + 2) % GSTAGES, i + 2);
        CP_COMMIT();
        CP_WAIT2();
        __syncthreads();

        const uint32_t stA = sb + (i % GSTAGES) * GSTAGE_B;
        const uint32_t stB = stA + 16384;

#pragma unroll
        for (int ks = 0; ks < 4; ++ks) {
            uint32_t af[4][4], bf[2][4];
#pragma unroll
            for (int mi = 0; mi < 4; ++mi) {
                const int row = a_row + mi * 16;
                const int kc  = 2 * ks + a_k;
                ldsm_x4(af[mi], stA + row * 128 + ((kc ^ (row & 7)) << 4));
            }
#pragma unroll
            for (int h = 0; h < 2; ++h) {
                const int row = b_row + h * 16;
                const int kc  = 2 * ks + b_k;
                ldsm_x4(bf[h], stB + row * 128 + ((kc ^ (row & 7)) << 4));
            }
#pragma unroll
            for (int mi = 0; mi < 4; ++mi)
#pragma unroll
                for (int nj = 0; nj < 4; ++nj)
                    mma_f16(acc[mi][nj], af[mi], &bf[nj >> 1][(nj & 1) * 2]);
        }
        __syncthreads();
    }

    const int g = lane >> 2, tg = lane & 3;
#pragma unroll
    for (int mi = 0; mi < 4; ++mi) {
        const int r0 = m0 + wm * 64 + mi * 16 + g;
#pragma unroll
        for (int nj = 0; nj < 4; ++nj) {
            const int col = n0 + wn * 32 + nj * 8 + tg * 2;
            float b0 = 0.0f, b1 = 0.0f;
            if (bias) { b0 = bias[col]; b1 = bias[col + 1]; }
            float2 o0 = make_float2(acc[mi][nj][0] + b0, acc[mi][nj][1] + b1);
            float2 o1 = make_float2(acc[mi][nj][2] + b0, acc[mi][nj][3] + b1);
            *(float2*)&C[(size_t)r0 * Nglob + col]       = o0;
            *(float2*)&C[(size_t)(r0 + 8) * Nglob + col] = o1;
        }
    }
}

// =============================================================================
// Attention (unchanged): one block per point, 8 warps = 8 heads.
// =============================================================================
__global__ void __launch_bounds__(256) attn_kernel()
{
    const int point = blockIdx.x;
    const int warp  = threadIdx.x >> 5;
    const int lane  = threadIdx.x & 31;
    const int b     = point >> 13;
    const int baseb = b * NN;

    const int* idxp = g_IDX + (size_t)point * 8;
    const float2 qh = *(const float2*)&g_QKV[(size_t)point * NQKV + warp * DHD + lane * 2];

    float dots[8];
    int   nbs[8];
#pragma unroll
    for (int k = 0; k < 8; ++k) {
        const int nb = idxp[k];
        nbs[k] = nb;
        const float2 kk = *(const float2*)&g_QKV[(size_t)(baseb + nb) * NQKV + INNER + warp * DHD + lane * 2];
        float d = qh.x * kk.x + qh.y * kk.y;
#pragma unroll
        for (int o = 16; o; o >>= 1) d += __shfl_xor_sync(0xffffffffu, d, o);
        dots[k] = d * 0.125f;
    }

    float m = dots[0];
#pragma unroll
    for (int k = 1; k < 8; ++k) m = fmaxf(m, dots[k]);
    float e[8], s = 0.0f;
#pragma unroll
    for (int k = 0; k < 8; ++k) { e[k] = expf(dots[k] - m); s += e[k]; }
    const float inv = 1.0f / s;

    float2 acc = make_float2(0.0f, 0.0f);
#pragma unroll
    for (int k = 0; k < 8; ++k) {
        const float2 vv = *(const float2*)&g_QKV[(size_t)(baseb + nbs[k]) * NQKV + 2 * INNER + warp * DHD + lane * 2];
        const float a = e[k] * inv;
        acc.x = fmaf(a, vv.x, acc.x);
        acc.y = fmaf(a, vv.y, acc.y);
    }

    __half hx, lx, hy, ly;
    split_f16(acc.x, hx, lx);
    split_f16(acc.y, hy, ly);
    __half2 hp; hp.x = hx; hp.y = hy;
    __half2 lp; lp.x = lx; lp.y = ly;
    __half* r = g_AT2 + (size_t)point * K2_OUT + warp * DHD + lane * 2;
    *(__half2*)(r)         = hp;
    *(__half2*)(r + INNER) = lp;
}

// =============================================================================
extern "C" void kernel_launch(void* const* d_in, const int* in_sizes, int n_in,
                              void* d_out, int out_size)
{
    const float* x    = (const float*)d_in[0];
    const float* pos  = (const float*)d_in[1];
    const float* Wq   = (const float*)d_in[2];
    const float* Wkv  = (const float*)d_in[3];
    const float* Wout = (const float*)d_in[4];
    const float* bout = (const float*)d_in[5];
    float* out = (float*)d_out;

    cudaFuncSetAttribute(gemm_mma_kernel,
                         cudaFuncAttributeMaxDynamicSharedMemorySize, GEMM_SMEM);
    cudaFuncSetAttribute(knn_scan_kernel,
                         cudaFuncAttributeMaxDynamicSharedMemorySize, KNN_SMEM);

    __half *pX2, *pWT, *pWTO, *pAT2;
    float *pQKV;
    cudaGetSymbolAddress((void**)&pX2,  g_X2);
    cudaGetSymbolAddress((void**)&pWT,  g_WT);
    cudaGetSymbolAddress((void**)&pWTO, g_WTO);
    cudaGetSymbolAddress((void**)&pQKV, g_QKV);
    cudaGetSymbolAddress((void**)&pAT2, g_AT2);

    // knn_scan at the deterministically-profiled 4th launch slot.
    conv_x_kernel<<<MTOT * DD / 256, 256>>>(x);
    conv_wqkv_kernel<<<NQKV * DD / 256, 256>>>(Wq, Wkv);
    conv_wout_kernel<<<DD * INNER / 256, 256>>>(Wout);

    // 4) KNN scan (branchless, buffered) — profiled this round
    knn_scan_kernel<<<dim3(MTOT / 256, NSLICE), 256, KNN_SMEM>>>(pos);

    // 5) KNN merge (8-way sorted merge, tie-break on index)
    knn_merge_kernel<<<MTOT / 256, 256>>>();

    // 6) fused QKV = x @ [Wq|Wkv]
    gemm_mma_kernel<<<dim3(NQKV / 128, MTOT / 128), 256, GEMM_SMEM>>>(
        pX2, pWT, pQKV, nullptr, NQKV, K2_QKV);

    // 7) neighbor attention
    attn_kernel<<<MTOT, 256>>>();

    // 8) out = ATT @ Wout + bout
    gemm_mma_kernel<<<dim3(DD / 128, MTOT / 128), 256, GEMM_SMEM>>>(
        pAT2, pWTO, out, bout, DD, K2_OUT);
}

// round 11
// speedup vs baseline: 1.9279x; 1.1053x over previous
#include <cuda_runtime.h>
#include <cuda_fp16.h>
#include <math.h>
#include <stdint.h>

// Problem constants
#define BB    2
#define NN    8192
#define DD    256
#define HH    8
#define DHD   64
#define KNB   8
#define INNER 512
#define MTOT  (BB*NN)        // 16384
#define NQKV  (3*INNER)      // 1536 = Q | K | V

// 2-term fp16 split as extended-K plain GEMM
#define K2_QKV (2*DD)        // 512
#define K2_OUT (2*INNER)     // 1024

// KNN slicing
#define NSLICE 8
#define SLICE  (NN / NSLICE)   // 1024 candidates per slice
#define KCAP   16              // per-thread append buffer entries

// ---------------- static device scratch ----------------
__device__ __half g_X2 [(size_t)MTOT * K2_QKV];
__device__ __half g_WT [(size_t)NQKV * K2_QKV];
__device__ __half g_WTO[(size_t)DD * K2_OUT];
__device__ float  g_QKV[(size_t)MTOT * NQKV];
__device__ __half g_AT2[(size_t)MTOT * K2_OUT];
__device__ int    g_IDX[(size_t)MTOT * KNB];
__device__ float  g_PD [(size_t)MTOT * NSLICE * KNB];   // partial top-8 dists
__device__ int    g_PI [(size_t)MTOT * NSLICE * KNB];   // partial top-8 idxs

__device__ __forceinline__ uint32_t smem_u32(const void* p) {
    uint32_t a;
    asm("{ .reg .u64 t; cvta.to.shared.u64 t, %1; cvt.u32.u64 %0, t; }" : "=r"(a) : "l"(p));
    return a;
}
__device__ __forceinline__ void cp_async16(uint32_t s, const void* g) {
    asm volatile("cp.async.cg.shared.global [%0], [%1], 16;" :: "r"(s), "l"(g));
}
#define CP_COMMIT()  asm volatile("cp.async.commit_group;" ::: "memory")
#define CP_WAIT2()   asm volatile("cp.async.wait_group 2;" ::: "memory")

__device__ __forceinline__ void split_f16(float v, __half& h, __half& l) {
    h = __float2half(v);
    l = __float2half(v - __half2float(h));
}

// =============================================================================
// KNN scan: lane-per-query, branchless buffered selection.
// Round-11 inner loop: distances for 8 candidates computed in plain C++
// (pipelined LDS.128, no clobbers), then 8 compact predicated appends —
// each a single asm carrying setp + @p st.shared.v2 + @p coff+=2048.
// Lazy threshold (8th-best, updated only at rare warp-collective flushes)
// only over-appends; flush drains in append(=index) order with strict-< ->
// exact jax.lax.top_k tie semantics.
// grid = (MTOT/256, NSLICE), block = 256. Dynamic smem 60KB.
// =============================================================================
#define KNN_SMEM (16384 + 12288 + 256 * KCAP * 8)   // s_c4 + s_raw + buffer

__global__ void __launch_bounds__(256) knn_scan_kernel(const float* __restrict__ pos)
{
    extern __shared__ char sm[];
    float4* s_c4  = (float4*)sm;                         // 16KB
    float*  s_raw = (float*)(sm + 16384);                // 12KB
    float2* s_buf = (float2*)(sm + 16384 + 12288);       // 32KB: [entry][tid]

    const int tid   = threadIdx.x;
    const int q     = blockIdx.x * 256 + tid;            // no batch straddle
    const int slice = blockIdx.y;
    const int b     = q >> 13;
    const int qn    = q & (NN - 1);
    const float* posb = pos + (size_t)b * NN * 3;

    const float qx2 = -2.0f * posb[qn * 3 + 0];
    const float qy2 = -2.0f * posb[qn * 3 + 1];
    const float qz2 = -2.0f * posb[qn * 3 + 2];

    // stage this slice's 1024 positions (3072 floats = 768 float4)
    {
        const float4* src = (const float4*)(posb + (size_t)slice * SLICE * 3);
#pragma unroll
        for (int i = 0; i < 3; ++i)
            ((float4*)s_raw)[tid + 256 * i] = src[tid + 256 * i];
    }
    __syncthreads();
#pragma unroll
    for (int i = 0; i < 4; ++i) {
        const int c = tid + 256 * i;
        const float cx = s_raw[c * 3 + 0];
        const float cy = s_raw[c * 3 + 1];
        const float cz = s_raw[c * 3 + 2];
        s_c4[c] = make_float4(cx, cy, cz, cx * cx + cy * cy + cz * cz);
    }
    __syncthreads();

    const float INF = __int_as_float(0x7f800000);
    float bd[8]; int bi[8];
#pragma unroll
    for (int j = 0; j < 8; ++j) { bd[j] = INF; bi[j] = 0x7fffffff; }
    float thr = INF;
    uint32_t coff = 0;                                   // count * 2048 (bytes)
    const int cbase = slice * SLICE;
    const uint32_t sbuf_tid = smem_u32(s_buf) + tid * 8;

    // flush: drain buffers of ALL lanes together (rare, warp-uniform entry)
    auto flush = [&]() {
        int count = (int)(coff >> 11);
        int mx = count;
#pragma unroll
        for (int o = 16; o; o >>= 1) mx = max(mx, __shfl_xor_sync(0xffffffffu, mx, o));
        for (int k = 0; k < mx; ++k) {
            const float2 e = s_buf[k * 256 + tid];
            if (k < count && e.x < bd[7]) {
                bd[7] = e.x; bi[7] = __float_as_int(e.y);
#pragma unroll
                for (int u = 7; u > 0; --u) {
                    if (bd[u] < bd[u - 1]) {            // strict: stable on ties
                        float tf = bd[u - 1]; bd[u - 1] = bd[u]; bd[u] = tf;
                        int   ti = bi[u - 1]; bi[u - 1] = bi[u]; bi[u] = ti;
                    }
                }
            }
        }
        thr = bd[7];
        coff = 0;
    };

    for (int c0 = 0; c0 < SLICE; c0 += 8) {
        // batch distance computation: pipelined broadcast LDS, no clobbers
        float t[8];
#pragma unroll
        for (int u = 0; u < 8; ++u) {
            const float4 p = s_c4[c0 + u];
            // d2 - |q|^2 = |c|^2 - 2 q.c  (constant shift: same ordering & ties)
            t[u] = fmaf(p.x, qx2, fmaf(p.y, qy2, fmaf(p.z, qz2, p.w)));
        }
        // compact appends: setp + @p store + @p bump, single asm each
#pragma unroll
        for (int u = 0; u < 8; ++u) {
            asm volatile(
                "{\n\t.reg .pred p;\n\t.reg .u32 a;\n\t"
                "setp.lt.f32 p, %1, %2;\n\t"
                "add.u32 a, %4, %0;\n\t"
                "@p st.shared.v2.f32 [a], {%1, %3};\n\t"
                "@p add.u32 %0, %0, 2048;\n\t}"
                : "+r"(coff)
                : "f"(t[u]), "f"(thr),
                  "f"(__int_as_float(cbase + c0 + u)), "r"(sbuf_tid)
                : "memory");
        }
        if (__ballot_sync(0xffffffffu, coff >= (KCAP - 8) * 2048))   // warp-uniform
            flush();
    }
    flush();

    float* pd = g_PD + ((size_t)q * NSLICE + slice) * 8;
    int*   pi = g_PI + ((size_t)q * NSLICE + slice) * 8;
#pragma unroll
    for (int j = 0; j < 8; ++j) { pd[j] = bd[j]; pi[j] = bi[j]; }
}

// =============================================================================
// KNN merge: per query, 8-way merge of sorted 8-lists with (dist, idx)
// tie-break (lower index wins) — exact jax.lax.top_k order.
// =============================================================================
__global__ void __launch_bounds__(256) knn_merge_kernel()
{
    const int q = blockIdx.x * 256 + threadIdx.x;
    const float* pd = g_PD + (size_t)q * (NSLICE * 8);
    const int*   pi = g_PI + (size_t)q * (NSLICE * 8);
    const float INF = __int_as_float(0x7f800000);

    float hd[NSLICE]; int hi_[NSLICE]; int pp[NSLICE];
#pragma unroll
    for (int s = 0; s < NSLICE; ++s) {
        hd[s] = pd[s * 8]; hi_[s] = pi[s * 8]; pp[s] = 0;
    }

    int out[8];
#pragma unroll
    for (int r = 0; r < 8; ++r) {
        float bdv = hd[0]; int biv = hi_[0]; int sel = 0;
#pragma unroll
        for (int s = 1; s < NSLICE; ++s)
            if (hd[s] < bdv || (hd[s] == bdv && hi_[s] < biv)) {
                bdv = hd[s]; biv = hi_[s]; sel = s;
            }
        out[r] = biv;
#pragma unroll
        for (int s = 0; s < NSLICE; ++s)
            if (sel == s) {
                ++pp[s];
                const bool ok = pp[s] < 8;
                hd[s]  = ok ? pd[s * 8 + pp[s]] : INF;
                hi_[s] = ok ? pi[s * 8 + pp[s]] : 0x7fffffff;
            }
    }
    *(int4*)&g_IDX[(size_t)q * 8]     = make_int4(out[0], out[1], out[2], out[3]);
    *(int4*)&g_IDX[(size_t)q * 8 + 4] = make_int4(out[4], out[5], out[6], out[7]);
}

// =============================================================================
// Conversions: fp32 -> fp16 (A: hi|lo split, B: hi duplicated), extended-K.
// =============================================================================
__global__ void __launch_bounds__(256) conv_x_kernel(const float* __restrict__ x)
{
    const int idx = blockIdx.x * 256 + threadIdx.x;
    const int row = idx >> 8, k = idx & 255;
    __half h, l;
    split_f16(x[idx], h, l);
    __half* r = g_X2 + (size_t)row * K2_QKV;
    r[k] = h; r[DD + k] = l;
}

__global__ void __launch_bounds__(256) conv_wqkv_kernel(const float* __restrict__ Wq,
                                                        const float* __restrict__ Wkv)
{
    const int idx = blockIdx.x * 256 + threadIdx.x;
    const int n = idx >> 8, k = idx & 255;
    const float v = (n < INNER) ? Wq[(size_t)k * INNER + n]
                                : Wkv[(size_t)k * (2 * INNER) + (n - INNER)];
    const __half h = __float2half(v);
    __half* r = g_WT + (size_t)n * K2_QKV;
    r[k] = h; r[DD + k] = h;
}

__global__ void __launch_bounds__(256) conv_wout_kernel(const float* __restrict__ Wout)
{
    const int idx = blockIdx.x * 256 + threadIdx.x;
    const int n = idx >> 9, k = idx & 511;
    const __half h = __float2half(Wout[(size_t)k * DD + n]);
    __half* r = g_WTO + (size_t)n * K2_OUT;
    r[k] = h; r[INNER + k] = h;
}

// =============================================================================
// fp16 tensor-core GEMM via mma.sync (unchanged — 82.5us @ tensor 51% on QKV).
// =============================================================================
#define GSTAGES   3
#define GSTAGE_B  32768
#define GEMM_SMEM (GSTAGES * GSTAGE_B)        // 96 KB

__device__ __forceinline__ void mma_f16(float* d, const uint32_t* a, const uint32_t* b)
{
    asm volatile(
        "mma.sync.aligned.m16n8k16.row.col.f32.f16.f16.f32 "
        "{%0,%1,%2,%3}, {%4,%5,%6,%7}, {%8,%9}, {%0,%1,%2,%3};"
        : "+f"(d[0]), "+f"(d[1]), "+f"(d[2]), "+f"(d[3])
        : "r"(a[0]), "r"(a[1]), "r"(a[2]), "r"(a[3]), "r"(b[0]), "r"(b[1]));
}

__device__ __forceinline__ void ldsm_x4(uint32_t* r, uint32_t a)
{
    asm volatile("ldmatrix.sync.aligned.m8n8.x4.shared.b16 {%0,%1,%2,%3}, [%4];"
        : "=r"(r[0]), "=r"(r[1]), "=r"(r[2]), "=r"(r[3]) : "r"(a));
}

__global__ void __launch_bounds__(256, 2) gemm_mma_kernel(
    const __half* __restrict__ A,
    const __half* __restrict__ Bt,
    float* __restrict__ C, const float* __restrict__ bias,
    int Nglob, int K2)
{
    extern __shared__ char smem[];
    const uint32_t sb = smem_u32(smem);
    const int tid  = threadIdx.x;
    const int warp = tid >> 5, lane = tid & 31;
    const int wm = warp & 1, wn = warp >> 1;
    const int m0 = blockIdx.y * 128, n0 = blockIdx.x * 128;
    const int nch = K2 >> 6;

    float acc[4][4][4];
#pragma unroll
    for (int i = 0; i < 4; ++i)
#pragma unroll
        for (int j = 0; j < 4; ++j)
#pragma unroll
            for (int t = 0; t < 4; ++t) acc[i][j][t] = 0.0f;

    const int a_row = wm * 64 + (lane & 15);
    const int a_k   = (lane >> 4);
    const int b_row = wn * 32 + ((lane & 16) >> 1) + (lane & 7);
    const int b_k   = ((lane >> 3) & 1);

    auto load_stage = [&](int s, int kc) {
        const uint32_t st = sb + s * GSTAGE_B;
#pragma unroll
        for (int it = 0; it < 4; ++it) {
            const int idx = it * 256 + tid;
            const int row = idx >> 3, c = idx & 7;
            cp_async16(st + row * 128 + ((c ^ (row & 7)) << 4),
                       A + (size_t)(m0 + row) * K2 + kc * 64 + c * 8);
        }
#pragma unroll
        for (int it = 0; it < 4; ++it) {
            const int idx = it * 256 + tid;
            const int row = idx >> 3, c = idx & 7;
            cp_async16(st + 16384 + row * 128 + ((c ^ (row & 7)) << 4),
                       Bt + (size_t)(n0 + row) * K2 + kc * 64 + c * 8);
        }
    };

    load_stage(0, 0); CP_COMMIT();
    load_stage(1, 1); CP_COMMIT();

    for (int i = 0; i < nch; ++i) {
        if (i + 2 < nch) load_stage((i + 2) % GSTAGES, i + 2);
        CP_COMMIT();
        CP_WAIT2();
        __syncthreads();

        const uint32_t stA = sb + (i % GSTAGES) * GSTAGE_B;
        const uint32_t stB = stA + 16384;

#pragma unroll
        for (int ks = 0; ks < 4; ++ks) {
            uint32_t af[4][4], bf[2][4];
#pragma unroll
            for (int mi = 0; mi < 4; ++mi) {
                const int row = a_row + mi * 16;
                const int kc  = 2 * ks + a_k;
                ldsm_x4(af[mi], stA + row * 128 + ((kc ^ (row & 7)) << 4));
            }
#pragma unroll
            for (int h = 0; h < 2; ++h) {
                const int row = b_row + h * 16;
                const int kc  = 2 * ks + b_k;
                ldsm_x4(bf[h], stB + row * 128 + ((kc ^ (row & 7)) << 4));
            }
#pragma unroll
            for (int mi = 0; mi < 4; ++mi)
#pragma unroll
                for (int nj = 0; nj < 4; ++nj)
                    mma_f16(acc[mi][nj], af[mi], &bf[nj >> 1][(nj & 1) * 2]);
        }
        __syncthreads();
    }

    const int g = lane >> 2, tg = lane & 3;
#pragma unroll
    for (int mi = 0; mi < 4; ++mi) {
        const int r0 = m0 + wm * 64 + mi * 16 + g;
#pragma unroll
        for (int nj = 0; nj < 4; ++nj) {
            const int col = n0 + wn * 32 + nj * 8 + tg * 2;
            float b0 = 0.0f, b1 = 0.0f;
            if (bias) { b0 = bias[col]; b1 = bias[col + 1]; }
            float2 o0 = make_float2(acc[mi][nj][0] + b0, acc[mi][nj][1] + b1);
            float2 o1 = make_float2(acc[mi][nj][2] + b0, acc[mi][nj][3] + b1);
            *(float2*)&C[(size_t)r0 * Nglob + col]       = o0;
            *(float2*)&C[(size_t)(r0 + 8) * Nglob + col] = o1;
        }
    }
}

// =============================================================================
// Attention (unchanged): one block per point, 8 warps = 8 heads.
// =============================================================================
__global__ void __launch_bounds__(256) attn_kernel()
{
    const int point = blockIdx.x;
    const int warp  = threadIdx.x >> 5;
    const int lane  = threadIdx.x & 31;
    const int b     = point >> 13;
    const int baseb = b * NN;

    const int* idxp = g_IDX + (size_t)point * 8;
    const float2 qh = *(const float2*)&g_QKV[(size_t)point * NQKV + warp * DHD + lane * 2];

    float dots[8];
    int   nbs[8];
#pragma unroll
    for (int k = 0; k < 8; ++k) {
        const int nb = idxp[k];
        nbs[k] = nb;
        const float2 kk = *(const float2*)&g_QKV[(size_t)(baseb + nb) * NQKV + INNER + warp * DHD + lane * 2];
        float d = qh.x * kk.x + qh.y * kk.y;
#pragma unroll
        for (int o = 16; o; o >>= 1) d += __shfl_xor_sync(0xffffffffu, d, o);
        dots[k] = d * 0.125f;
    }

    float m = dots[0];
#pragma unroll
    for (int k = 1; k < 8; ++k) m = fmaxf(m, dots[k]);
    float e[8], s = 0.0f;
#pragma unroll
    for (int k = 0; k < 8; ++k) { e[k] = expf(dots[k] - m); s += e[k]; }
    const float inv = 1.0f / s;

    float2 acc = make_float2(0.0f, 0.0f);
#pragma unroll
    for (int k = 0; k < 8; ++k) {
        const float2 vv = *(const float2*)&g_QKV[(size_t)(baseb + nbs[k]) * NQKV + 2 * INNER + warp * DHD + lane * 2];
        const float a = e[k] * inv;
        acc.x = fmaf(a, vv.x, acc.x);
        acc.y = fmaf(a, vv.y, acc.y);
    }

    __half hx, lx, hy, ly;
    split_f16(acc.x, hx, lx);
    split_f16(acc.y, hy, ly);
    __half2 hp; hp.x = hx; hp.y = hy;
    __half2 lp; lp.x = lx; lp.y = ly;
    __half* r = g_AT2 + (size_t)point * K2_OUT + warp * DHD + lane * 2;
    *(__half2*)(r)         = hp;
    *(__half2*)(r + INNER) = lp;
}

// =============================================================================
extern "C" void kernel_launch(void* const* d_in, const int* in_sizes, int n_in,
                              void* d_out, int out_size)
{
    const float* x    = (const float*)d_in[0];
    const float* pos  = (const float*)d_in[1];
    const float* Wq   = (const float*)d_in[2];
    const float* Wkv  = (const float*)d_in[3];
    const float* Wout = (const float*)d_in[4];
    const float* bout = (const float*)d_in[5];
    float* out = (float*)d_out;

    cudaFuncSetAttribute(gemm_mma_kernel,
                         cudaFuncAttributeMaxDynamicSharedMemorySize, GEMM_SMEM);
    cudaFuncSetAttribute(knn_scan_kernel,
                         cudaFuncAttributeMaxDynamicSharedMemorySize, KNN_SMEM);

    __half *pX2, *pWT, *pWTO, *pAT2;
    float *pQKV;
    cudaGetSymbolAddress((void**)&pX2,  g_X2);
    cudaGetSymbolAddress((void**)&pWT,  g_WT);
    cudaGetSymbolAddress((void**)&pWTO, g_WTO);
    cudaGetSymbolAddress((void**)&pQKV, g_QKV);
    cudaGetSymbolAddress((void**)&pAT2, g_AT2);

    // knn_scan at the deterministically-profiled 4th launch slot.
    conv_x_kernel<<<MTOT * DD / 256, 256>>>(x);
    conv_wqkv_kernel<<<NQKV * DD / 256, 256>>>(Wq, Wkv);
    conv_wout_kernel<<<DD * INNER / 256, 256>>>(Wout);

    // 4) KNN scan (branchless, batched LDS + compact appends) — profiled
    knn_scan_kernel<<<dim3(MTOT / 256, NSLICE), 256, KNN_SMEM>>>(pos);

    // 5) KNN merge (8-way sorted merge, tie-break on index)
    knn_merge_kernel<<<MTOT / 256, 256>>>();

    // 6) fused QKV = x @ [Wq|Wkv]
    gemm_mma_kernel<<<dim3(NQKV / 128, MTOT / 128), 256, GEMM_SMEM>>>(
        pX2, pWT, pQKV, nullptr, NQKV, K2_QKV);

    // 7) neighbor attention
    attn_kernel<<<MTOT, 256>>>();

    // 8) out = ATT @ Wout + bout
    gemm_mma_kernel<<<dim3(DD / 128, MTOT / 128), 256, GEMM_SMEM>>>(
        pAT2, pWTO, out, bout, DD, K2_OUT);
}